// round 14
// baseline (speedup 1.0000x reference)
#include <cuda_runtime.h>
#include <cuda_fp16.h>
#include <math.h>
#include <stdint.h>

#define NEGINF -1000000.0f

// Problem constants
#define BATCH 8
#define SEQ   2048
#define EMB   512
#define BSZ   (BATCH * SEQ)

// Scratch (no allocs allowed).
// g_X16: fp16 copies of Xq/Xk/Xv. g_Wt16: fp16 W transposed [z][n][k].
// g_Q, g_K: fp16 [b][s][e]. g_V: fp16 transposed per batch [b][e][s].
// g_P16: fp16 softmax(P) for pv.
__device__ __half g_X16[(size_t)3 * BSZ * EMB];
__device__ __half g_Wt16[(size_t)3 * EMB * EMB];
__device__ __half g_Q[(size_t)BSZ * EMB];
__device__ __half g_K[(size_t)BSZ * EMB];
__device__ __half g_V[(size_t)BSZ * EMB];
__device__ __half g_P16[(size_t)BATCH * SEQ * SEQ];

#define BM 128
#define BN 128
#define BKH 64         // k-chunk in fp16 elements; 128B per smem row
#define STAGES 3       // ring depth, prefetch distance 2
#define ROWB 144       // smem row stride bytes (128B data + 16B pad)
#define TILEB (128 * ROWB)   // one operand stage: 18432 B

__device__ __forceinline__ void mma_f16(float (&d)[4], const uint32_t (&a)[4],
                                        const uint32_t (&b)[2]) {
    asm volatile(
        "mma.sync.aligned.m16n8k16.row.col.f32.f16.f16.f32 "
        "{%0,%1,%2,%3}, {%4,%5,%6,%7}, {%8,%9}, {%0,%1,%2,%3};\n"
        : "+f"(d[0]), "+f"(d[1]), "+f"(d[2]), "+f"(d[3])
        : "r"(a[0]), "r"(a[1]), "r"(a[2]), "r"(a[3]), "r"(b[0]), "r"(b[1]));
}

#define LDSM_X4(r0, r1, r2, r3, addr)                                        \
    asm volatile("ldmatrix.sync.aligned.m8n8.x4.shared.b16 {%0,%1,%2,%3}, [%4];" \
                 : "=r"(r0), "=r"(r1), "=r"(r2), "=r"(r3) : "r"(addr))

__device__ __forceinline__ void cp16(const void* dst_smem, const void* src) {
    uint32_t d = (uint32_t)__cvta_generic_to_shared(dst_smem);
    asm volatile("cp.async.cg.shared.global [%0], [%1], 16;" :: "r"(d), "l"(src));
}
#define CP_COMMIT() asm volatile("cp.async.commit_group;" ::: "memory")
#define CP_WAIT1()  asm volatile("cp.async.wait_group 1;" ::: "memory")

// Shared fp16 GEMM core: both operands [row][128B+pad] smem tiles, ldmatrix
// b16 fragments, k-chunk 64 halves. Validated base address formulas.
#define GEMM_FRAG_COMPUTE_F16(aBase, bBase, curOff)                          \
    do {                                                                     \
        _Pragma("unroll")                                                    \
        for (int ks = 0; ks < 4; ks++) {                                     \
            uint32_t af[4][4], bf[4][2];                                     \
            _Pragma("unroll")                                                \
            for (int mi = 0; mi < 4; mi++)                                   \
                LDSM_X4(af[mi][0], af[mi][1], af[mi][2], af[mi][3],          \
                        (aBase) + (curOff) + mi * (16 * ROWB) + ks * 32);    \
            _Pragma("unroll")                                                \
            for (int np = 0; np < 2; np++)                                   \
                LDSM_X4(bf[2 * np][0], bf[2 * np][1],                        \
                        bf[2 * np + 1][0], bf[2 * np + 1][1],                \
                        (bBase) + (curOff) + np * (16 * ROWB) + ks * 32);    \
            _Pragma("unroll")                                                \
            for (int mi = 0; mi < 4; mi++)                                   \
                _Pragma("unroll")                                            \
                for (int ni = 0; ni < 4; ni++)                               \
                    mma_f16(acc[mi][ni], af[mi], bf[ni]);                    \
        }                                                                    \
    } while (0)

// ---------------------------------------------------------------------------
// Prep 1: Xq/Xk/Xv fp32 -> fp16 (g_X16). 8 elems per thread.
// ---------------------------------------------------------------------------
__global__ __launch_bounds__(256)
void x16_kernel(const float* __restrict__ Xq, const float* __restrict__ Xk,
                const float* __restrict__ Xv)
{
    const float* S = (blockIdx.y == 0) ? Xq : (blockIdx.y == 1) ? Xk : Xv;
    __half* D = g_X16 + (size_t)blockIdx.y * BSZ * EMB;
    size_t base = ((size_t)blockIdx.x * 256 + threadIdx.x) * 8;
    float4 a = *(const float4*)&S[base];
    float4 b = *(const float4*)&S[base + 4];
    __half2 h[4] = {__floats2half2_rn(a.x, a.y), __floats2half2_rn(a.z, a.w),
                    __floats2half2_rn(b.x, b.y), __floats2half2_rn(b.z, b.w)};
    *(uint4*)&D[base] = *(uint4*)h;
}

// ---------------------------------------------------------------------------
// Prep 2: W [k][n] fp32 -> g_Wt16 [z][n][k] fp16 (transpose + convert).
// ---------------------------------------------------------------------------
__global__ void wt16_kernel(const float* __restrict__ Wq, const float* __restrict__ Wk,
                            const float* __restrict__ Wv)
{
    const float* S = (blockIdx.z == 0) ? Wq : (blockIdx.z == 1) ? Wk : Wv;
    __half* D = g_Wt16 + (size_t)blockIdx.z * EMB * EMB;
    __shared__ float t[32][33];
    int x = blockIdx.x * 32, y = blockIdx.y * 32;
    int tx = threadIdx.x, ty = threadIdx.y;
#pragma unroll
    for (int i = ty; i < 32; i += 8) t[i][tx] = S[(size_t)(y + i) * EMB + x + tx];
    __syncthreads();
#pragma unroll
    for (int i = ty; i < 32; i += 8)
        D[(size_t)(x + i) * EMB + y + tx] = __float2half_rn(t[tx][i]);
}

// ---------------------------------------------------------------------------
// Kernel 1: projections, fp16 core. A = g_X16 rows, B = g_Wt16 [n][k] rows.
// iters = 512/64 = 8. Epilogue: alpha scale; z==2 writes V transposed [e][s].
// ---------------------------------------------------------------------------
__global__ __launch_bounds__(256, 2)
void proj_kernel(float inv_scale)
{
    extern __shared__ char dsm[];

    int z = blockIdx.z;
    const __half* Ab = g_X16 + (size_t)z * BSZ * EMB;
    const __half* Bw = g_Wt16 + (size_t)z * EMB * EMB;
    __half* C = (z == 0) ? g_Q : (z == 1) ? g_K : g_V;
    float alpha = (z == 2) ? 1.0f : inv_scale;

    int tid = threadIdx.x;
    int wid = tid >> 5, lane = tid & 31;
    int gid = lane >> 2, tig = lane & 3;
    int wm = wid >> 2, wn = wid & 3;
    int m0 = blockIdx.y * BM, n0 = blockIdx.x * BN;

    int srow = tid >> 3;
    int ssegB = (tid & 7) << 4;
    int ssegH = (tid & 7) << 3;

    uint32_t smem_u32 = (uint32_t)__cvta_generic_to_shared(dsm);
    uint32_t aBase = smem_u32 + (uint32_t)(wm * 64 + (lane & 15)) * ROWB + ((lane >> 4) << 4);
    uint32_t bBase = smem_u32 + (uint32_t)(STAGES * TILEB)
                   + (uint32_t)(wn * 32 + ((lane >> 4) << 3) + (lane & 7)) * ROWB
                   + (((lane >> 3) & 1) << 4);

    float acc[4][4][4];
#pragma unroll
    for (int i = 0; i < 4; i++)
#pragma unroll
        for (int j = 0; j < 4; j++)
#pragma unroll
            for (int r = 0; r < 4; r++) acc[i][j][r] = 0.f;

#define PJ_STAGE(buf, k0)                                                     \
    do {                                                                      \
        _Pragma("unroll")                                                     \
        for (int p = 0; p < 4; p++) {                                         \
            int row = p * 32 + srow;                                          \
            cp16(dsm + (buf) * TILEB + row * ROWB + ssegB,                    \
                 &Ab[(size_t)(m0 + row) * EMB + (k0) + ssegH]);               \
            cp16(dsm + STAGES * TILEB + (buf) * TILEB + row * ROWB + ssegB,   \
                 &Bw[(size_t)(n0 + row) * EMB + (k0) + ssegH]);               \
        }                                                                     \
        CP_COMMIT();                                                          \
    } while (0)

    const int iters = EMB / BKH;   // 8
    PJ_STAGE(0, 0);
    PJ_STAGE(1, BKH);

    int cur = 0, wr = 2;
    for (int it = 0; it < iters; it++) {
        CP_WAIT1();
        __syncthreads();
        if (it + 2 < iters) PJ_STAGE(wr, (it + 2) * BKH);
        else CP_COMMIT();
        uint32_t curOff = (uint32_t)cur * TILEB;
        GEMM_FRAG_COMPUTE_F16(aBase, bBase, curOff);
        cur = (cur == STAGES - 1) ? 0 : cur + 1;
        wr  = (wr  == STAGES - 1) ? 0 : wr + 1;
    }
#undef PJ_STAGE

    if (z != 2) {
#pragma unroll
        for (int mi = 0; mi < 4; mi++) {
            int r = m0 + wm * 64 + mi * 16 + gid;
#pragma unroll
            for (int ni = 0; ni < 4; ni++) {
                int c = n0 + wn * 32 + ni * 8 + tig * 2;
                *(__half2*)&C[(size_t)r * EMB + c] =
                    __floats2half2_rn(acc[mi][ni][0] * alpha, acc[mi][ni][1] * alpha);
                *(__half2*)&C[(size_t)(r + 8) * EMB + c] =
                    __floats2half2_rn(acc[mi][ni][2] * alpha, acc[mi][ni][3] * alpha);
            }
        }
    } else {
        // V transposed: [b][e][s]
        int bb = m0 >> 11;
        __half* Vb = C + (size_t)bb * SEQ * EMB;
#pragma unroll
        for (int mi = 0; mi < 4; mi++) {
            int s = (m0 & 2047) + wm * 64 + mi * 16 + gid;
#pragma unroll
            for (int ni = 0; ni < 4; ni++) {
                int c = n0 + wn * 32 + ni * 8 + tig * 2;
                Vb[(size_t)c * SEQ + s]           = __float2half_rn(acc[mi][ni][0]);
                Vb[(size_t)(c + 1) * SEQ + s]     = __float2half_rn(acc[mi][ni][1]);
                Vb[(size_t)c * SEQ + s + 8]       = __float2half_rn(acc[mi][ni][2]);
                Vb[(size_t)(c + 1) * SEQ + s + 8] = __float2half_rn(acc[mi][ni][3]);
            }
        }
    }
}

// ---------------------------------------------------------------------------
// Kernel 2: masked scores. Q,K fp16 [row][k] tiles. iters = 8.
// ---------------------------------------------------------------------------
__global__ __launch_bounds__(256, 2)
void scores_kernel(const int* __restrict__ mask, float* __restrict__ out_p)
{
    extern __shared__ char dsm[];

    int b = blockIdx.z;
    const __half* Qb = g_Q + (size_t)b * SEQ * EMB;
    const __half* Kb = g_K + (size_t)b * SEQ * EMB;
    const int*   Mb  = mask + (size_t)b * SEQ * SEQ;
    float*       Cb  = out_p + (size_t)b * SEQ * SEQ;

    int tid = threadIdx.x;
    int wid = tid >> 5, lane = tid & 31;
    int gid = lane >> 2, tig = lane & 3;
    int wm = wid >> 2, wn = wid & 3;
    int m0 = blockIdx.y * BM, n0 = blockIdx.x * BN;

    int srow = tid >> 3;
    int ssegB = (tid & 7) << 4;
    int ssegH = (tid & 7) << 3;

    uint32_t smem_u32 = (uint32_t)__cvta_generic_to_shared(dsm);
    uint32_t aBase = smem_u32 + (uint32_t)(wm * 64 + (lane & 15)) * ROWB + ((lane >> 4) << 4);
    uint32_t bBase = smem_u32 + (uint32_t)(STAGES * TILEB)
                   + (uint32_t)(wn * 32 + ((lane >> 4) << 3) + (lane & 7)) * ROWB
                   + (((lane >> 3) & 1) << 4);

    float acc[4][4][4];
#pragma unroll
    for (int i = 0; i < 4; i++)
#pragma unroll
        for (int j = 0; j < 4; j++)
#pragma unroll
            for (int r = 0; r < 4; r++) acc[i][j][r] = 0.f;

#define SC_STAGE(buf, k0)                                                     \
    do {                                                                      \
        _Pragma("unroll")                                                     \
        for (int p = 0; p < 4; p++) {                                         \
            int row = p * 32 + srow;                                          \
            cp16(dsm + (buf) * TILEB + row * ROWB + ssegB,                    \
                 &Qb[(size_t)(m0 + row) * EMB + (k0) + ssegH]);               \
            cp16(dsm + STAGES * TILEB + (buf) * TILEB + row * ROWB + ssegB,   \
                 &Kb[(size_t)(n0 + row) * EMB + (k0) + ssegH]);               \
        }                                                                     \
        CP_COMMIT();                                                          \
    } while (0)

    const int iters = EMB / BKH;   // 8
    SC_STAGE(0, 0);
    SC_STAGE(1, BKH);

    int cur = 0, wr = 2;
    for (int it = 0; it < iters; it++) {
        CP_WAIT1();
        __syncthreads();
        if (it + 2 < iters) SC_STAGE(wr, (it + 2) * BKH);
        else CP_COMMIT();
        uint32_t curOff = (uint32_t)cur * TILEB;
        GEMM_FRAG_COMPUTE_F16(aBase, bBase, curOff);
        cur = (cur == STAGES - 1) ? 0 : cur + 1;
        wr  = (wr  == STAGES - 1) ? 0 : wr + 1;
    }
#undef SC_STAGE

#pragma unroll
    for (int mi = 0; mi < 4; mi++) {
        int r = m0 + wm * 64 + mi * 16 + gid;
#pragma unroll
        for (int ni = 0; ni < 4; ni++) {
            int c = n0 + wn * 32 + ni * 8 + tig * 2;
            size_t o0 = (size_t)r * SEQ + c;
            size_t o1 = (size_t)(r + 8) * SEQ + c;
            int2 mv0 = *(const int2*)&Mb[o0];
            int2 mv1 = *(const int2*)&Mb[o1];
            *(float2*)&Cb[o0] = make_float2(mv0.x ? acc[mi][ni][0] : NEGINF,
                                            mv0.y ? acc[mi][ni][1] : NEGINF);
            *(float2*)&Cb[o1] = make_float2(mv1.x ? acc[mi][ni][2] : NEGINF,
                                            mv1.y ? acc[mi][ni][3] : NEGINF);
        }
    }
}

// ---------------------------------------------------------------------------
// Kernel 3: row softmax. fp32 P to d_out + fp16 P to g_P16. Masked = 0.
// ---------------------------------------------------------------------------
__global__ __launch_bounds__(256)
void softmax_kernel(float* __restrict__ P)
{
    float* prow = P + (size_t)blockIdx.x * SEQ;
    __half* prow16 = g_P16 + (size_t)blockIdx.x * SEQ;
    int tid = threadIdx.x;
    int lane = tid & 31, warp = tid >> 5;
    __shared__ float red[8];

    float4 v0 = ((const float4*)prow)[tid];
    float4 v1 = ((const float4*)prow)[tid + 256];
    float x[8] = {v0.x, v0.y, v0.z, v0.w, v1.x, v1.y, v1.z, v1.w};

    float m = x[0];
#pragma unroll
    for (int i = 1; i < 8; i++) m = fmaxf(m, x[i]);
#pragma unroll
    for (int o = 16; o > 0; o >>= 1) m = fmaxf(m, __shfl_xor_sync(0xFFFFFFFFu, m, o));
    if (lane == 0) red[warp] = m;
    __syncthreads();
    m = red[0];
#pragma unroll
    for (int i = 1; i < 8; i++) m = fmaxf(m, red[i]);

    if (m == NEGINF) {  // fully masked row
        float4 zz = make_float4(0.f, 0.f, 0.f, 0.f);
        ((float4*)prow)[tid] = zz;
        ((float4*)prow)[tid + 256] = zz;
        uint2 hz = make_uint2(0u, 0u);
        *(uint2*)&prow16[tid * 4] = hz;
        *(uint2*)&prow16[(tid + 256) * 4] = hz;
        return;
    }

    float e[8], s = 0.f;
#pragma unroll
    for (int i = 0; i < 8; i++) { e[i] = __expf(x[i] - m); s += e[i]; }
#pragma unroll
    for (int o = 16; o > 0; o >>= 1) s += __shfl_xor_sync(0xFFFFFFFFu, s, o);
    __syncthreads();
    if (lane == 0) red[warp] = s;
    __syncthreads();
    s = 0.f;
#pragma unroll
    for (int i = 0; i < 8; i++) s += red[i];
    float inv = 1.0f / s;

    float p0 = e[0] * inv, p1 = e[1] * inv, p2 = e[2] * inv, p3 = e[3] * inv;
    float p4 = e[4] * inv, p5 = e[5] * inv, p6 = e[6] * inv, p7 = e[7] * inv;

    ((float4*)prow)[tid]       = make_float4(p0, p1, p2, p3);
    ((float4*)prow)[tid + 256] = make_float4(p4, p5, p6, p7);

    *(__half2*)&prow16[tid * 4]             = __floats2half2_rn(p0, p1);
    *(__half2*)&prow16[tid * 4 + 2]         = __floats2half2_rn(p2, p3);
    *(__half2*)&prow16[(tid + 256) * 4]     = __floats2half2_rn(p4, p5);
    *(__half2*)&prow16[(tid + 256) * 4 + 2] = __floats2half2_rn(p6, p7);
}

// ---------------------------------------------------------------------------
// Kernel 4: z = P @ V. A = g_P16 [q][k]; B = g_V [e][s]. iters = 32.
// ---------------------------------------------------------------------------
__global__ __launch_bounds__(256, 2)
void pv_kernel(float* __restrict__ out_z)
{
    extern __shared__ char dsm[];

    int b = blockIdx.z;
    const __half* Ab = g_P16 + (size_t)b * SEQ * SEQ;
    const __half* Vt = g_V + (size_t)b * SEQ * EMB;   // [e][s]
    float*        Cb = out_z + (size_t)b * SEQ * EMB;

    int tid = threadIdx.x;
    int wid = tid >> 5, lane = tid & 31;
    int gid = lane >> 2, tig = lane & 3;
    int wm = wid >> 2, wn = wid & 3;
    int m0 = blockIdx.y * BM, n0 = blockIdx.x * BN;

    int srow = tid >> 3;
    int ssegB = (tid & 7) << 4;
    int ssegH = (tid & 7) << 3;

    uint32_t smem_u32 = (uint32_t)__cvta_generic_to_shared(dsm);
    uint32_t aBase = smem_u32 + (uint32_t)(wm * 64 + (lane & 15)) * ROWB + ((lane >> 4) << 4);
    uint32_t bBase = smem_u32 + (uint32_t)(STAGES * TILEB)
                   + (uint32_t)(wn * 32 + ((lane >> 4) << 3) + (lane & 7)) * ROWB
                   + (((lane >> 3) & 1) << 4);

    float acc[4][4][4];
#pragma unroll
    for (int i = 0; i < 4; i++)
#pragma unroll
        for (int j = 0; j < 4; j++)
#pragma unroll
            for (int r = 0; r < 4; r++) acc[i][j][r] = 0.f;

#define PV_STAGE(buf, k0)                                                     \
    do {                                                                      \
        _Pragma("unroll")                                                     \
        for (int p = 0; p < 4; p++) {                                         \
            int row = p * 32 + srow;                                          \
            cp16(dsm + (buf) * TILEB + row * ROWB + ssegB,                    \
                 &Ab[(size_t)(m0 + row) * SEQ + (k0) + ssegH]);               \
            cp16(dsm + STAGES * TILEB + (buf) * TILEB + row * ROWB + ssegB,   \
                 &Vt[(size_t)(n0 + row) * SEQ + (k0) + ssegH]);               \
        }                                                                     \
        CP_COMMIT();                                                          \
    } while (0)

    const int iters = SEQ / BKH;   // 32
    PV_STAGE(0, 0);
    PV_STAGE(1, BKH);

    int cur = 0, wr = 2;
    for (int it = 0; it < iters; it++) {
        CP_WAIT1();
        __syncthreads();
        if (it + 2 < iters) PV_STAGE(wr, (it + 2) * BKH);
        else CP_COMMIT();
        uint32_t curOff = (uint32_t)cur * TILEB;
        GEMM_FRAG_COMPUTE_F16(aBase, bBase, curOff);
        cur = (cur == STAGES - 1) ? 0 : cur + 1;
        wr  = (wr  == STAGES - 1) ? 0 : wr + 1;
    }
#undef PV_STAGE

#pragma unroll
    for (int mi = 0; mi < 4; mi++) {
        int r = m0 + wm * 64 + mi * 16 + gid;
#pragma unroll
        for (int ni = 0; ni < 4; ni++) {
            int c = n0 + wn * 32 + ni * 8 + tig * 2;
            *(float2*)&Cb[(size_t)r * EMB + c] = make_float2(acc[mi][ni][0], acc[mi][ni][1]);
            *(float2*)&Cb[(size_t)(r + 8) * EMB + c] = make_float2(acc[mi][ni][2], acc[mi][ni][3]);
        }
    }
}

// ---------------------------------------------------------------------------
// Launch. Inputs: Xin_q, Xin_k, Xin_v, mask, Wq, Wk, Wv.
// Output: z [8,2048,512] then attn_p [8,2048,2048], fp32.
// ---------------------------------------------------------------------------
extern "C" void kernel_launch(void* const* d_in, const int* in_sizes, int n_in,
                              void* d_out, int out_size)
{
    const float* Xq = (const float*)d_in[0];
    const float* Xk = (const float*)d_in[1];
    const float* Xv = (const float*)d_in[2];
    const int*   mk = (const int*)d_in[3];
    const float* Wq = (const float*)d_in[4];
    const float* Wk = (const float*)d_in[5];
    const float* Wv = (const float*)d_in[6];

    float* out_z = (float*)d_out;
    float* out_p = out_z + (size_t)BATCH * SEQ * EMB;

    const float inv_scale = 0.21022410381342864f;  // 1/512^(1/4)

    const int GEMM_SMEM = 2 * STAGES * TILEB;   // 110592 B
    cudaFuncSetAttribute(proj_kernel, cudaFuncAttributeMaxDynamicSharedMemorySize, GEMM_SMEM);
    cudaFuncSetAttribute(scores_kernel, cudaFuncAttributeMaxDynamicSharedMemorySize, GEMM_SMEM);
    cudaFuncSetAttribute(pv_kernel, cudaFuncAttributeMaxDynamicSharedMemorySize, GEMM_SMEM);

    x16_kernel<<<dim3((size_t)BSZ * EMB / 2048, 3), 256>>>(Xq, Xk, Xv);
    wt16_kernel<<<dim3(16, 16, 3), dim3(32, 8)>>>(Wq, Wk, Wv);
    proj_kernel<<<dim3(EMB / BN, BSZ / BM, 3), 256, GEMM_SMEM>>>(inv_scale);
    scores_kernel<<<dim3(SEQ / BN, SEQ / BM, BATCH), 256, GEMM_SMEM>>>(mk, out_p);
    softmax_kernel<<<BSZ, 256>>>(out_p);
    pv_kernel<<<dim3(EMB / BN, SEQ / BM, BATCH), 256, GEMM_SMEM>>>(out_z);
}

// round 15
// speedup vs baseline: 1.1865x; 1.1865x over previous
#include <cuda_runtime.h>
#include <cuda_fp16.h>
#include <math.h>
#include <stdint.h>

#define NEGINF -1000000.0f

// Problem constants
#define BATCH 8
#define SEQ   2048
#define EMB   512
#define BSZ   (BATCH * SEQ)

// Scratch (no allocs allowed).
// g_Q, g_K: fp16 [b][s][e]. g_V: fp16 TRANSPOSED per batch [b][e][s].
// g_P16: fp16 copy of softmax(P) for pv's A operand.
__device__ __half g_Q[(size_t)BSZ * EMB];
__device__ __half g_K[(size_t)BSZ * EMB];
__device__ __half g_V[(size_t)BSZ * EMB];
__device__ __half g_P16[(size_t)BATCH * SEQ * SEQ];

#define BM 128
#define BN 128
#define BKH 64         // scores/pv k-chunk in fp16 elements; 128B per row
#define STAGES 3       // ring depth, prefetch distance 2
#define ROWB 144       // smem row stride bytes (128B data + 16B pad)
#define TILEB (128 * ROWB)   // one operand stage: 18432 B

__device__ __forceinline__ uint32_t f2tf(float f) {
    uint32_t r;
    asm("cvt.rna.tf32.f32 %0, %1;" : "=r"(r) : "f"(f));
    return r;
}

__device__ __forceinline__ void mma_tf32(float (&d)[4], const uint32_t (&a)[4],
                                         const uint32_t (&b)[2]) {
    asm volatile(
        "mma.sync.aligned.m16n8k8.row.col.f32.tf32.tf32.f32 "
        "{%0,%1,%2,%3}, {%4,%5,%6,%7}, {%8,%9}, {%0,%1,%2,%3};\n"
        : "+f"(d[0]), "+f"(d[1]), "+f"(d[2]), "+f"(d[3])
        : "r"(a[0]), "r"(a[1]), "r"(a[2]), "r"(a[3]), "r"(b[0]), "r"(b[1]));
}

__device__ __forceinline__ void mma_f16(float (&d)[4], const uint32_t (&a)[4],
                                        const uint32_t (&b)[2]) {
    asm volatile(
        "mma.sync.aligned.m16n8k16.row.col.f32.f16.f16.f32 "
        "{%0,%1,%2,%3}, {%4,%5,%6,%7}, {%8,%9}, {%0,%1,%2,%3};\n"
        : "+f"(d[0]), "+f"(d[1]), "+f"(d[2]), "+f"(d[3])
        : "r"(a[0]), "r"(a[1]), "r"(a[2]), "r"(a[3]), "r"(b[0]), "r"(b[1]));
}

#define LDSM_X4(r0, r1, r2, r3, addr)                                        \
    asm volatile("ldmatrix.sync.aligned.m8n8.x4.shared.b16 {%0,%1,%2,%3}, [%4];" \
                 : "=r"(r0), "=r"(r1), "=r"(r2), "=r"(r3) : "r"(addr))

__device__ __forceinline__ void cp16(const void* dst_smem, const void* src) {
    uint32_t d = (uint32_t)__cvta_generic_to_shared(dst_smem);
    asm volatile("cp.async.cg.shared.global [%0], [%1], 16;" :: "r"(d), "l"(src));
}
#define CP_COMMIT() asm volatile("cp.async.commit_group;" ::: "memory")
#define CP_WAIT1()  asm volatile("cp.async.wait_group 1;" ::: "memory")

// ---------------------------------------------------------------------------
// Kernel 1: projections (register-pipelined tf32 GEMM over fp32 inputs).
// Epilogue emits fp16: Q,K row-major; V transposed per batch [e][s] via a
// smem-staged coalesced write (fixes 16x sector amplification of the old
// scattered half stores).
// ---------------------------------------------------------------------------
#define PJ_PIPE_WORDS (2 * 16 * 132)      // one operand, both buffers
#define PJ_SM_WORDS   8704                // max(2*PJ_PIPE_WORDS, 128*136*2/4)

__global__ __launch_bounds__(256, 2)
void proj_kernel(const float* __restrict__ Xq, const float* __restrict__ Xk,
                 const float* __restrict__ Xv, const float* __restrict__ Wq,
                 const float* __restrict__ Wk, const float* __restrict__ Wv,
                 float inv_scale)
{
    __shared__ __align__(16) uint32_t smbuf[PJ_SM_WORDS];
    uint32_t (*As)[16][132] = (uint32_t (*)[16][132])smbuf;
    uint32_t (*Bs)[16][132] = (uint32_t (*)[16][132])(smbuf + PJ_PIPE_WORDS);

    const float* A; const float* W; __half* C; float alpha;
    int z = blockIdx.z;
    if (z == 0)      { A = Xq; W = Wq; C = g_Q; alpha = inv_scale; }
    else if (z == 1) { A = Xk; W = Wk; C = g_K; alpha = inv_scale; }
    else             { A = Xv; W = Wv; C = g_V; alpha = 1.0f; }

    const int K = 512, N = 512;
    const int PBK = 16;

    int tid = threadIdx.x;
    int wid = tid >> 5, lane = tid & 31;
    int gid = lane >> 2, tig = lane & 3;
    int wm = wid >> 2, wn = wid & 3;
    int m0 = blockIdx.y * BM, n0 = blockIdx.x * BN;

    int arow = tid >> 2;
    int acol = (tid & 3) << 2;
    int brow = tid >> 5;
    int bcol = (tid & 31) << 2;

    float acc[4][4][4];
#pragma unroll
    for (int i = 0; i < 4; i++)
#pragma unroll
        for (int j = 0; j < 4; j++)
#pragma unroll
            for (int r = 0; r < 4; r++) acc[i][j][r] = 0.f;

    float4 ra[2], rb[2];
#define PROJ_LDG(k0)                                                          \
    do {                                                                      \
        ra[0] = *(const float4*)&A[(size_t)(m0 + arow) * K + (k0) + acol];    \
        ra[1] = *(const float4*)&A[(size_t)(m0 + arow + 64) * K + (k0) + acol]; \
        rb[0] = *(const float4*)&W[(size_t)((k0) + brow) * N + n0 + bcol];    \
        rb[1] = *(const float4*)&W[(size_t)((k0) + brow + 8) * N + n0 + bcol]; \
    } while (0)
#define PROJ_STS(buf)                                                         \
    do {                                                                      \
        _Pragma("unroll")                                                     \
        for (int p = 0; p < 2; p++) {                                         \
            As[buf][acol + 0][arow + p * 64] = f2tf(ra[p].x);                 \
            As[buf][acol + 1][arow + p * 64] = f2tf(ra[p].y);                 \
            As[buf][acol + 2][arow + p * 64] = f2tf(ra[p].z);                 \
            As[buf][acol + 3][arow + p * 64] = f2tf(ra[p].w);                 \
            uint4 u = make_uint4(f2tf(rb[p].x), f2tf(rb[p].y),                \
                                 f2tf(rb[p].z), f2tf(rb[p].w));               \
            *(uint4*)&Bs[buf][brow + p * 8][bcol] = u;                        \
        }                                                                     \
    } while (0)

    PROJ_LDG(0);
    PROJ_STS(0);
    __syncthreads();

    const int iters = K / PBK;
    for (int it = 0; it < iters; it++) {
        int cur = it & 1;
        bool more = (it + 1 < iters);
        if (more) PROJ_LDG((it + 1) * PBK);
#pragma unroll
        for (int ks = 0; ks < 2; ks++) {
            int kk = ks * 8;
            uint32_t af[4][4], bf[4][2];
#pragma unroll
            for (int mi = 0; mi < 4; mi++) {
                int m = wm * 64 + mi * 16 + gid;
                af[mi][0] = As[cur][kk + tig][m];
                af[mi][1] = As[cur][kk + tig][m + 8];
                af[mi][2] = As[cur][kk + tig + 4][m];
                af[mi][3] = As[cur][kk + tig + 4][m + 8];
            }
#pragma unroll
            for (int ni = 0; ni < 4; ni++) {
                int n = wn * 32 + ni * 8 + gid;
                bf[ni][0] = Bs[cur][kk + tig][n];
                bf[ni][1] = Bs[cur][kk + tig + 4][n];
            }
#pragma unroll
            for (int mi = 0; mi < 4; mi++)
#pragma unroll
                for (int ni = 0; ni < 4; ni++)
                    mma_tf32(acc[mi][ni], af[mi], bf[ni]);
        }
        if (more) PROJ_STS(cur ^ 1);
        __syncthreads();
    }
#undef PROJ_LDG
#undef PROJ_STS

    if (z != 2) {
#pragma unroll
        for (int mi = 0; mi < 4; mi++) {
            int r = m0 + wm * 64 + mi * 16 + gid;
#pragma unroll
            for (int ni = 0; ni < 4; ni++) {
                int c = n0 + wn * 32 + ni * 8 + tig * 2;
                *(__half2*)&C[(size_t)r * EMB + c] =
                    __floats2half2_rn(acc[mi][ni][0] * alpha, acc[mi][ni][1] * alpha);
                *(__half2*)&C[(size_t)(r + 8) * EMB + c] =
                    __floats2half2_rn(acc[mi][ni][2] * alpha, acc[mi][ni][3] * alpha);
            }
        }
    } else {
        // V transposed [b][e][s] via smem staging:
        // vt[e_local][s_local], row stride 136 halfs (272B: 16B-aligned,
        // 17-phase bank walk -> conflict-free LDS.128 on readout).
        __half* vt = (__half*)smbuf;
        // pipeline smem fully consumed; last loop iteration ended in __syncthreads
#pragma unroll
        for (int mi = 0; mi < 4; mi++) {
            int s = wm * 64 + mi * 16 + gid;        // block-local s
#pragma unroll
            for (int ni = 0; ni < 4; ni++) {
                int c = wn * 32 + ni * 8 + tig * 2; // block-local e
                vt[c * 136 + s]           = __float2half_rn(acc[mi][ni][0]);
                vt[(c + 1) * 136 + s]     = __float2half_rn(acc[mi][ni][1]);
                vt[c * 136 + s + 8]       = __float2half_rn(acc[mi][ni][2]);
                vt[(c + 1) * 136 + s + 8] = __float2half_rn(acc[mi][ni][3]);
            }
        }
        __syncthreads();
        int bb = m0 >> 11;                 // batch (tile never straddles)
        int sblk = m0 & 2047;
        __half* Vb = C + (size_t)bb * SEQ * EMB;
        int row = tid >> 1;                // e_local 0..127
        int hoff = (tid & 1) * 64;         // first/second half of s-row
#pragma unroll
        for (int j = 0; j < 8; j++) {
            *(uint4*)&Vb[(size_t)(n0 + row) * SEQ + sblk + hoff + j * 8] =
                *(uint4*)&vt[row * 136 + hoff + j * 8];
        }
    }
}

// ---------------------------------------------------------------------------
// Shared fp16 GEMM core (scores/pv): validated ldmatrix fragment layout.
// ---------------------------------------------------------------------------
#define GEMM_FRAG_COMPUTE_F16(aBase, bBase, curOff)                          \
    do {                                                                     \
        _Pragma("unroll")                                                    \
        for (int ks = 0; ks < 4; ks++) {                                     \
            uint32_t af[4][4], bf[4][2];                                     \
            _Pragma("unroll")                                                \
            for (int mi = 0; mi < 4; mi++)                                   \
                LDSM_X4(af[mi][0], af[mi][1], af[mi][2], af[mi][3],          \
                        (aBase) + (curOff) + mi * (16 * ROWB) + ks * 32);    \
            _Pragma("unroll")                                                \
            for (int np = 0; np < 2; np++)                                   \
                LDSM_X4(bf[2 * np][0], bf[2 * np][1],                        \
                        bf[2 * np + 1][0], bf[2 * np + 1][1],                \
                        (bBase) + (curOff) + np * (16 * ROWB) + ks * 32);    \
            _Pragma("unroll")                                                \
            for (int mi = 0; mi < 4; mi++)                                   \
                _Pragma("unroll")                                            \
                for (int ni = 0; ni < 4; ni++)                               \
                    mma_f16(acc[mi][ni], af[mi], bf[ni]);                    \
        }                                                                    \
    } while (0)

// ---------------------------------------------------------------------------
// Kernel 2: masked scores. Mask prefetched into a 64-bit register BEFORE the
// mainloop (latency hidden behind the cp.async prologue fill).
// ---------------------------------------------------------------------------
__global__ __launch_bounds__(256, 2)
void scores_kernel(const int* __restrict__ mask, float* __restrict__ out_p)
{
    extern __shared__ char dsm[];

    int b = blockIdx.z;
    const __half* Qb = g_Q + (size_t)b * SEQ * EMB;
    const __half* Kb = g_K + (size_t)b * SEQ * EMB;
    const int*   Mb  = mask + (size_t)b * SEQ * SEQ;
    float*       Cb  = out_p + (size_t)b * SEQ * SEQ;

    int tid = threadIdx.x;
    int wid = tid >> 5, lane = tid & 31;
    int gid = lane >> 2, tig = lane & 3;
    int wm = wid >> 2, wn = wid & 3;
    int m0 = blockIdx.y * BM, n0 = blockIdx.x * BN;

    int srow = tid >> 3;
    int ssegB = (tid & 7) << 4;
    int ssegH = (tid & 7) << 3;

    uint32_t smem_u32 = (uint32_t)__cvta_generic_to_shared(dsm);
    uint32_t aBase = smem_u32 + (uint32_t)(wm * 64 + (lane & 15)) * ROWB + ((lane >> 4) << 4);
    uint32_t bBase = smem_u32 + (uint32_t)(STAGES * TILEB)
                   + (uint32_t)(wn * 32 + ((lane >> 4) << 3) + (lane & 7)) * ROWB
                   + (((lane >> 3) & 1) << 4);

    float acc[4][4][4];
#pragma unroll
    for (int i = 0; i < 4; i++)
#pragma unroll
        for (int j = 0; j < 4; j++)
#pragma unroll
            for (int r = 0; r < 4; r++) acc[i][j][r] = 0.f;

#define SC_STAGE(buf, k0)                                                     \
    do {                                                                      \
        _Pragma("unroll")                                                     \
        for (int p = 0; p < 4; p++) {                                         \
            int row = p * 32 + srow;                                          \
            cp16(dsm + (buf) * TILEB + row * ROWB + ssegB,                    \
                 &Qb[(size_t)(m0 + row) * EMB + (k0) + ssegH]);               \
            cp16(dsm + STAGES * TILEB + (buf) * TILEB + row * ROWB + ssegB,   \
                 &Kb[(size_t)(n0 + row) * EMB + (k0) + ssegH]);               \
        }                                                                     \
        CP_COMMIT();                                                          \
    } while (0)

    const int iters = EMB / BKH;   // 8
    SC_STAGE(0, 0);
    SC_STAGE(1, BKH);

    // ---- mask prefetch into bitset (overlaps the pipeline prologue) ----
    uint64_t mbits = 0;
#pragma unroll
    for (int mi = 0; mi < 4; mi++) {
        int r = m0 + wm * 64 + mi * 16 + gid;
#pragma unroll
        for (int ni = 0; ni < 4; ni++) {
            int c = n0 + wn * 32 + ni * 8 + tig * 2;
            int2 mv0 = *(const int2*)&Mb[(size_t)r * SEQ + c];
            int2 mv1 = *(const int2*)&Mb[(size_t)(r + 8) * SEQ + c];
            int k = (mi * 4 + ni) * 4;
            mbits |= (uint64_t)(mv0.x != 0) << k;
            mbits |= (uint64_t)(mv0.y != 0) << (k + 1);
            mbits |= (uint64_t)(mv1.x != 0) << (k + 2);
            mbits |= (uint64_t)(mv1.y != 0) << (k + 3);
        }
    }

    int cur = 0, wr = 2;
    for (int it = 0; it < iters; it++) {
        CP_WAIT1();
        __syncthreads();
        if (it + 2 < iters) SC_STAGE(wr, (it + 2) * BKH);
        else CP_COMMIT();
        uint32_t curOff = (uint32_t)cur * TILEB;
        GEMM_FRAG_COMPUTE_F16(aBase, bBase, curOff);
        cur = (cur == STAGES - 1) ? 0 : cur + 1;
        wr  = (wr  == STAGES - 1) ? 0 : wr + 1;
    }
#undef SC_STAGE

#pragma unroll
    for (int mi = 0; mi < 4; mi++) {
        int r = m0 + wm * 64 + mi * 16 + gid;
#pragma unroll
        for (int ni = 0; ni < 4; ni++) {
            int c = n0 + wn * 32 + ni * 8 + tig * 2;
            size_t o0 = (size_t)r * SEQ + c;
            size_t o1 = (size_t)(r + 8) * SEQ + c;
            int k = (mi * 4 + ni) * 4;
            *(float2*)&Cb[o0] = make_float2(
                (mbits >> k) & 1 ? acc[mi][ni][0] : NEGINF,
                (mbits >> (k + 1)) & 1 ? acc[mi][ni][1] : NEGINF);
            *(float2*)&Cb[o1] = make_float2(
                (mbits >> (k + 2)) & 1 ? acc[mi][ni][2] : NEGINF,
                (mbits >> (k + 3)) & 1 ? acc[mi][ni][3] : NEGINF);
        }
    }
}

// ---------------------------------------------------------------------------
// Kernel 3: row softmax. fp32 P to d_out + fp16 P to g_P16. Masked = 0.
// ---------------------------------------------------------------------------
__global__ __launch_bounds__(256)
void softmax_kernel(float* __restrict__ P)
{
    float* prow = P + (size_t)blockIdx.x * SEQ;
    __half* prow16 = g_P16 + (size_t)blockIdx.x * SEQ;
    int tid = threadIdx.x;
    int lane = tid & 31, warp = tid >> 5;
    __shared__ float red[8];

    float4 v0 = ((const float4*)prow)[tid];
    float4 v1 = ((const float4*)prow)[tid + 256];
    float x[8] = {v0.x, v0.y, v0.z, v0.w, v1.x, v1.y, v1.z, v1.w};

    float m = x[0];
#pragma unroll
    for (int i = 1; i < 8; i++) m = fmaxf(m, x[i]);
#pragma unroll
    for (int o = 16; o > 0; o >>= 1) m = fmaxf(m, __shfl_xor_sync(0xFFFFFFFFu, m, o));
    if (lane == 0) red[warp] = m;
    __syncthreads();
    m = red[0];
#pragma unroll
    for (int i = 1; i < 8; i++) m = fmaxf(m, red[i]);

    if (m == NEGINF) {  // fully masked row
        float4 zz = make_float4(0.f, 0.f, 0.f, 0.f);
        ((float4*)prow)[tid] = zz;
        ((float4*)prow)[tid + 256] = zz;
        uint2 hz = make_uint2(0u, 0u);
        *(uint2*)&prow16[tid * 4] = hz;
        *(uint2*)&prow16[(tid + 256) * 4] = hz;
        return;
    }

    float e[8], s = 0.f;
#pragma unroll
    for (int i = 0; i < 8; i++) { e[i] = __expf(x[i] - m); s += e[i]; }
#pragma unroll
    for (int o = 16; o > 0; o >>= 1) s += __shfl_xor_sync(0xFFFFFFFFu, s, o);
    __syncthreads();
    if (lane == 0) red[warp] = s;
    __syncthreads();
    s = 0.f;
#pragma unroll
    for (int i = 0; i < 8; i++) s += red[i];
    float inv = 1.0f / s;

    float p0 = e[0] * inv, p1 = e[1] * inv, p2 = e[2] * inv, p3 = e[3] * inv;
    float p4 = e[4] * inv, p5 = e[5] * inv, p6 = e[6] * inv, p7 = e[7] * inv;

    ((float4*)prow)[tid]       = make_float4(p0, p1, p2, p3);
    ((float4*)prow)[tid + 256] = make_float4(p4, p5, p6, p7);

    *(__half2*)&prow16[tid * 4]             = __floats2half2_rn(p0, p1);
    *(__half2*)&prow16[tid * 4 + 2]         = __floats2half2_rn(p2, p3);
    *(__half2*)&prow16[(tid + 256) * 4]     = __floats2half2_rn(p4, p5);
    *(__half2*)&prow16[(tid + 256) * 4 + 2] = __floats2half2_rn(p6, p7);
}

// ---------------------------------------------------------------------------
// Kernel 4: z = P @ V. A = g_P16 [q][k]; B = g_V [e][s]. iters = 32.
// ---------------------------------------------------------------------------
__global__ __launch_bounds__(256, 2)
void pv_kernel(float* __restrict__ out_z)
{
    extern __shared__ char dsm[];

    int b = blockIdx.z;
    const __half* Ab = g_P16 + (size_t)b * SEQ * SEQ;
    const __half* Vt = g_V + (size_t)b * SEQ * EMB;   // [e][s]
    float*        Cb = out_z + (size_t)b * SEQ * EMB;

    int tid = threadIdx.x;
    int wid = tid >> 5, lane = tid & 31;
    int gid = lane >> 2, tig = lane & 3;
    int wm = wid >> 2, wn = wid & 3;
    int m0 = blockIdx.y * BM, n0 = blockIdx.x * BN;

    int srow = tid >> 3;
    int ssegB = (tid & 7) << 4;
    int ssegH = (tid & 7) << 3;

    uint32_t smem_u32 = (uint32_t)__cvta_generic_to_shared(dsm);
    uint32_t aBase = smem_u32 + (uint32_t)(wm * 64 + (lane & 15)) * ROWB + ((lane >> 4) << 4);
    uint32_t bBase = smem_u32 + (uint32_t)(STAGES * TILEB)
                   + (uint32_t)(wn * 32 + ((lane >> 4) << 3) + (lane & 7)) * ROWB
                   + (((lane >> 3) & 1) << 4);

    float acc[4][4][4];
#pragma unroll
    for (int i = 0; i < 4; i++)
#pragma unroll
        for (int j = 0; j < 4; j++)
#pragma unroll
            for (int r = 0; r < 4; r++) acc[i][j][r] = 0.f;

#define PV_STAGE(buf, k0)                                                     \
    do {                                                                      \
        _Pragma("unroll")                                                     \
        for (int p = 0; p < 4; p++) {                                         \
            int row = p * 32 + srow;                                          \
            cp16(dsm + (buf) * TILEB + row * ROWB + ssegB,                    \
                 &Ab[(size_t)(m0 + row) * SEQ + (k0) + ssegH]);               \
            cp16(dsm + STAGES * TILEB + (buf) * TILEB + row * ROWB + ssegB,   \
                 &Vt[(size_t)(n0 + row) * SEQ + (k0) + ssegH]);               \
        }                                                                     \
        CP_COMMIT();                                                          \
    } while (0)

    const int iters = SEQ / BKH;   // 32
    PV_STAGE(0, 0);
    PV_STAGE(1, BKH);

    int cur = 0, wr = 2;
    for (int it = 0; it < iters; it++) {
        CP_WAIT1();
        __syncthreads();
        if (it + 2 < iters) PV_STAGE(wr, (it + 2) * BKH);
        else CP_COMMIT();
        uint32_t curOff = (uint32_t)cur * TILEB;
        GEMM_FRAG_COMPUTE_F16(aBase, bBase, curOff);
        cur = (cur == STAGES - 1) ? 0 : cur + 1;
        wr  = (wr  == STAGES - 1) ? 0 : wr + 1;
    }
#undef PV_STAGE

#pragma unroll
    for (int mi = 0; mi < 4; mi++) {
        int r = m0 + wm * 64 + mi * 16 + gid;
#pragma unroll
        for (int ni = 0; ni < 4; ni++) {
            int c = n0 + wn * 32 + ni * 8 + tig * 2;
            *(float2*)&Cb[(size_t)r * EMB + c] = make_float2(acc[mi][ni][0], acc[mi][ni][1]);
            *(float2*)&Cb[(size_t)(r + 8) * EMB + c] = make_float2(acc[mi][ni][2], acc[mi][ni][3]);
        }
    }
}

// ---------------------------------------------------------------------------
// Launch. Inputs: Xin_q, Xin_k, Xin_v, mask, Wq, Wk, Wv.
// Output: z [8,2048,512] then attn_p [8,2048,2048], fp32.
// ---------------------------------------------------------------------------
extern "C" void kernel_launch(void* const* d_in, const int* in_sizes, int n_in,
                              void* d_out, int out_size)
{
    const float* Xq = (const float*)d_in[0];
    const float* Xk = (const float*)d_in[1];
    const float* Xv = (const float*)d_in[2];
    const int*   mk = (const int*)d_in[3];
    const float* Wq = (const float*)d_in[4];
    const float* Wk = (const float*)d_in[5];
    const float* Wv = (const float*)d_in[6];

    float* out_z = (float*)d_out;
    float* out_p = out_z + (size_t)BATCH * SEQ * EMB;

    const float inv_scale = 0.21022410381342864f;  // 1/512^(1/4)

    const int GEMM_SMEM = 2 * STAGES * TILEB;   // 110592 B
    cudaFuncSetAttribute(scores_kernel, cudaFuncAttributeMaxDynamicSharedMemorySize, GEMM_SMEM);
    cudaFuncSetAttribute(pv_kernel, cudaFuncAttributeMaxDynamicSharedMemorySize, GEMM_SMEM);

    proj_kernel<<<dim3(EMB / BN, BSZ / BM, 3), 256>>>(Xq, Xk, Xv, Wq, Wk, Wv, inv_scale);
    scores_kernel<<<dim3(SEQ / BN, SEQ / BM, BATCH), 256, GEMM_SMEM>>>(mk, out_p);
    softmax_kernel<<<BSZ, 256>>>(out_p);
    pv_kernel<<<dim3(EMB / BN, SEQ / BM, BATCH), 256, GEMM_SMEM>>>(out_z);
}